// round 8
// baseline (speedup 1.0000x reference)
#include <cuda_runtime.h>
#include <cstdint>

// entmax-1.5 over rows, persistent-CTA cp.async pipeline.
// z = (mask? s : -1e4)*0.5; active iff z > rmax-1; tau = root of
// sum max((z-rmax)-tau,0)^2 = 1 in [-1,0]; p = max(z-(rmax+tau),0)^2.
// Warp 0: 10 bisections on ~90 register-resident actives + exact
// fixed-support closed form tau = (S1 - sqrt(S1^2 - k(S2-1)))/k.
//
// Pipeline: grid-stride rows; while processing row r from shared stage s,
// row r+stride streams into stage s^1 via cp.async.cg (L2-only). DRAM stays
// busy through the barrier/solve/store phases that starved it in R7.

constexpr int COLS    = 4096;
constexpr int THREADS = 256;
constexpr int PER     = COLS / THREADS;  // 16
constexpr int VEC     = PER / 4;         // 4
constexpr int NWARP   = THREADS / 32;    // 8
constexpr int NB      = 10;
constexpr int CAP     = 128;             // register fast path (4/lane)
constexpr int ACAP    = 1024;
constexpr int CTAS    = 444;             // 148 SMs * 3 CTAs
constexpr int DYN_SMEM = 2 * COLS * 4 * 2;  // 2 stages * (scores f32 + mask i32) = 64KB

__device__ __forceinline__ void cp_async16(void* dst_smem, const void* src_g) {
    uint32_t s = (uint32_t)__cvta_generic_to_shared(dst_smem);
    asm volatile("cp.async.cg.shared.global [%0], [%1], 16;\n" :: "r"(s), "l"(src_g));
}
__device__ __forceinline__ void cp_commit() {
    asm volatile("cp.async.commit_group;\n" ::: "memory");
}
__device__ __forceinline__ void cp_wait1() {
    asm volatile("cp.async.wait_group 1;\n" ::: "memory");
}
__device__ __forceinline__ void cp_wait0() {
    asm volatile("cp.async.wait_group 0;\n" ::: "memory");
}

__device__ __forceinline__ float warp_sum(float v) {
#pragma unroll
    for (int off = 16; off > 0; off >>= 1)
        v += __shfl_xor_sync(0xffffffffu, v, off);
    return v;
}

__global__ __launch_bounds__(THREADS) void entmax15_kernel(
    const float* __restrict__ scores,
    const int* __restrict__ mask,
    float* __restrict__ out,
    int rows)
{
    extern __shared__ char smraw[];
    float* s_sc = reinterpret_cast<float*>(smraw);              // [2][COLS]
    int*   s_mk = reinterpret_cast<int*>(smraw + 2 * COLS * 4); // [2][COLS]

    __shared__ float abuf[ACAP];
    __shared__ float sh_max[NWARP];
    __shared__ float sh_tau;
    __shared__ int   cnt;

    const int t    = threadIdx.x;
    const int wid  = t >> 5;
    const int lane = t & 31;
    const int stride = gridDim.x;

    // ---- Prologue: prefetch first row ----
    {
        int r0 = blockIdx.x;
        if (r0 < rows) {
            const float* gs = scores + (size_t)r0 * COLS;
            const int*   gm = mask   + (size_t)r0 * COLS;
#pragma unroll
            for (int c = 0; c < VEC; ++c) {
                int idx = c * (THREADS * 4) + t * 4;
                cp_async16(s_sc + idx, gs + idx);
                cp_async16(s_mk + idx, gm + idx);
            }
            cp_commit();
        }
    }

    int iter = 0;
    for (int r = blockIdx.x; r < rows; r += stride, ++iter) {
        const int stage = iter & 1;
        const int rn = r + stride;

        // Stage^1 buffer is free only after all threads finished the previous
        // iteration's reads of it.
        __syncthreads();

        if (rn < rows) {
            const float* gs = scores + (size_t)rn * COLS;
            const int*   gm = mask   + (size_t)rn * COLS;
            float* ds = s_sc + (stage ^ 1) * COLS;
            int*   dm = s_mk + (stage ^ 1) * COLS;
#pragma unroll
            for (int c = 0; c < VEC; ++c) {
                int idx = c * (THREADS * 4) + t * 4;
                cp_async16(ds + idx, gs + idx);
                cp_async16(dm + idx, gm + idx);
            }
            cp_commit();
            cp_wait1();   // current row's group complete; next row's in flight
        } else {
            cp_wait0();
        }
        __syncthreads();

        const float* zs = s_sc + stage * COLS;
        const int*   zm = s_mk + stage * COLS;

        // ---- Read shared once -> z regs; local max ----
        float z[PER];
        float lmax = -3.402823e38f;
#pragma unroll
        for (int c = 0; c < VEC; ++c) {
            const int idx = c * (THREADS * 4) + t * 4;
            float4 v  = *reinterpret_cast<const float4*>(zs + idx);
            int4   mm = *reinterpret_cast<const int4*>(zm + idx);
            float z0 = (mm.x ? v.x : -1.0e4f) * 0.5f;
            float z1 = (mm.y ? v.y : -1.0e4f) * 0.5f;
            float z2 = (mm.z ? v.z : -1.0e4f) * 0.5f;
            float z3 = (mm.w ? v.w : -1.0e4f) * 0.5f;
            z[c*4+0] = z0; z[c*4+1] = z1; z[c*4+2] = z2; z[c*4+3] = z3;
            lmax = fmaxf(lmax, fmaxf(fmaxf(z0, z1), fmaxf(z2, z3)));
        }

        // ---- Block max ----
#pragma unroll
        for (int off = 16; off > 0; off >>= 1)
            lmax = fmaxf(lmax, __shfl_xor_sync(0xffffffffu, lmax, off));
        if (lane == 0) sh_max[wid] = lmax;
        if (t == 0) cnt = 0;
        __syncthreads();
        float rmax = sh_max[0];
#pragma unroll
        for (int i = 1; i < NWARP; ++i) rmax = fmaxf(rmax, sh_max[i]);
        const float thr = rmax - 1.0f;

        // ---- Compact actives (store v = z - rmax) ----
#pragma unroll
        for (int i = 0; i < PER; ++i) {
            if (z[i] > thr) {
                int p = atomicAdd(&cnt, 1);   // warp-aggregated
                if (p < ACAP) abuf[p] = z[i] - rmax;
            }
        }
        __syncthreads();

        // ---- Warp 0 solves tau ----
        if (wid == 0) {
            const int n = cnt;   // >= 1
            float lo = -1.0f, hi = 0.0f;
            float tau;

            if (n <= CAP) {
                float v[4];
#pragma unroll
                for (int j = 0; j < 4; ++j) {
                    int i = lane + 32 * j;
                    v[j] = (i < n) ? abuf[i] : -2.0f;
                }
#pragma unroll 1
                for (int it = 0; it < NB; ++it) {
                    const float tm = 0.5f * (lo + hi);
                    float acc = 0.0f;
#pragma unroll
                    for (int j = 0; j < 4; ++j) {
                        float d = fmaxf(v[j] - tm, 0.0f);
                        acc = fmaf(d, d, acc);
                    }
                    if (warp_sum(acc) >= 1.0f) lo = tm; else hi = tm;
                }
                float k = 0.0f, S1 = 0.0f, S2 = 0.0f;
#pragma unroll
                for (int j = 0; j < 4; ++j)
                    if (v[j] > lo) { k += 1.0f; S1 += v[j]; S2 = fmaf(v[j], v[j], S2); }
                k = warp_sum(k); S1 = warp_sum(S1); S2 = warp_sum(S2);
                float disc = fmaxf(fmaf(S1, S1, -k * (S2 - 1.0f)), 0.0f);
                tau = (S1 - sqrtf(disc)) / k;
            } else if (n <= ACAP) {
#pragma unroll 1
                for (int it = 0; it < NB; ++it) {
                    const float tm = 0.5f * (lo + hi);
                    float acc = 0.0f;
                    for (int i = lane; i < n; i += 32) {
                        float d = fmaxf(abuf[i] - tm, 0.0f);
                        acc = fmaf(d, d, acc);
                    }
                    if (warp_sum(acc) >= 1.0f) lo = tm; else hi = tm;
                }
                float k = 0.0f, S1 = 0.0f, S2 = 0.0f;
                for (int i = lane; i < n; i += 32) {
                    float v = abuf[i];
                    if (v > lo) { k += 1.0f; S1 += v; S2 = fmaf(v, v, S2); }
                }
                k = warp_sum(k); S1 = warp_sum(S1); S2 = warp_sum(S2);
                float disc = fmaxf(fmaf(S1, S1, -k * (S2 - 1.0f)), 0.0f);
                tau = (S1 - sqrtf(disc)) / k;
            } else {
                // pathological: recompute z from the (still valid) raw stage
#pragma unroll 1
                for (int it = 0; it < NB; ++it) {
                    const float tm = 0.5f * (lo + hi);
                    float acc = 0.0f;
                    for (int i = lane; i < COLS; i += 32) {
                        float zi = (zm[i] ? zs[i] : -1.0e4f) * 0.5f - rmax;
                        float d = fmaxf(zi - tm, 0.0f);
                        acc = fmaf(d, d, acc);
                    }
                    if (warp_sum(acc) >= 1.0f) lo = tm; else hi = tm;
                }
                float k = 0.0f, S1 = 0.0f, S2 = 0.0f;
                for (int i = lane; i < COLS; i += 32) {
                    float v = (zm[i] ? zs[i] : -1.0e4f) * 0.5f - rmax;
                    if (v > lo) { k += 1.0f; S1 += v; S2 = fmaf(v, v, S2); }
                }
                k = warp_sum(k); S1 = warp_sum(S1); S2 = warp_sum(S2);
                float disc = fmaxf(fmaf(S1, S1, -k * (S2 - 1.0f)), 0.0f);
                tau = (S1 - sqrtf(disc)) / k;
            }
            if (lane == 0) sh_tau = tau;
        }
        __syncthreads();
        const float taup = sh_tau + rmax;

        // ---- Store p = max(z - taup, 0)^2 ----
        float* o = out + (size_t)r * COLS;
#pragma unroll
        for (int c = 0; c < VEC; ++c) {
            const int idx = c * (THREADS * 4) + t * 4;
            float d0 = fmaxf(z[c*4+0] - taup, 0.0f);
            float d1 = fmaxf(z[c*4+1] - taup, 0.0f);
            float d2 = fmaxf(z[c*4+2] - taup, 0.0f);
            float d3 = fmaxf(z[c*4+3] - taup, 0.0f);
            float4 p;
            p.x = d0*d0; p.y = d1*d1; p.z = d2*d2; p.w = d3*d3;
            __stcs(reinterpret_cast<float4*>(o + idx), p);
        }
    }
}

extern "C" void kernel_launch(void* const* d_in, const int* in_sizes, int n_in,
                              void* d_out, int out_size) {
    const float* scores = (const float*)d_in[0];
    const int*   mask   = (const int*)d_in[1];
    float* out = (float*)d_out;
    const int rows = in_sizes[0] / COLS;

    cudaFuncSetAttribute(entmax15_kernel,
                         cudaFuncAttributeMaxDynamicSharedMemorySize, DYN_SMEM);
    int grid = rows < CTAS ? rows : CTAS;
    entmax15_kernel<<<grid, THREADS, DYN_SMEM>>>(scores, mask, out, rows);
}

// round 9
// speedup vs baseline: 1.5175x; 1.5175x over previous
#include <cuda_runtime.h>

// entmax-1.5 over rows. zbuf holds z = (mask? s : -1e4)*0.5 (unshifted) in shared;
// active iff z > rmax-1; tau = root of sum max((z-rmax)-tau,0)^2 = 1 in [-1,0];
// p = max(z-(rmax+tau),0)^2. ~90/4096 elements active; warp 0 runs 10 bisections
// on register-resident actives + exact fixed-support closed form
//   tau = (S1 - sqrt(S1^2 - k(S2-1)))/k  over support {v > lo}.
//
// R9: 128-thread CTAs (one row each) -> ~18.5KB smem -> 12 CTAs/SM:
// 12 independent rows per SM decorrelate load/solve/store phases and keep DRAM
// busy; barriers span 4 warps; solve idles only 3 warps.

constexpr int COLS    = 4096;
constexpr int THREADS = 128;
constexpr int PER     = COLS / THREADS;  // 32
constexpr int VEC     = PER / 4;         // 8
constexpr int NWARP   = THREADS / 32;    // 4
constexpr int NB      = 10;
constexpr int CAP     = 128;             // register fast path (4/lane)
constexpr int ACAP    = 512;

__device__ __forceinline__ float warp_sum(float v) {
#pragma unroll
    for (int off = 16; off > 0; off >>= 1)
        v += __shfl_xor_sync(0xffffffffu, v, off);
    return v;
}

__global__ __launch_bounds__(THREADS, 12) void entmax15_kernel(
    const float* __restrict__ scores,
    const int* __restrict__ mask,
    float* __restrict__ out)
{
    __shared__ float zbuf[COLS];     // full row of z (unshifted)
    __shared__ float abuf[ACAP];     // compacted actives (v = z - rmax)
    __shared__ float sh_max[NWARP];
    __shared__ float sh_tau;
    __shared__ int   cnt;

    const size_t row = blockIdx.x;
    const float* s = scores + row * COLS;
    const int*   m = mask   + row * COLS;
    float* o = out + row * COLS;

    const int t    = threadIdx.x;
    const int wid  = t >> 5;
    const int lane = t & 31;

    // ---- Load, mask, *0.5 -> shared; track local max ----
    float lmax = -3.402823e38f;
#pragma unroll
    for (int c = 0; c < VEC; ++c) {
        const int idx = c * (THREADS * 4) + t * 4;
        float4 v  = __ldcs(reinterpret_cast<const float4*>(s + idx));
        int4   mm = __ldcs(reinterpret_cast<const int4*>(m + idx));
        float4 zz;
        zz.x = (mm.x ? v.x : -1.0e4f) * 0.5f;
        zz.y = (mm.y ? v.y : -1.0e4f) * 0.5f;
        zz.z = (mm.z ? v.z : -1.0e4f) * 0.5f;
        zz.w = (mm.w ? v.w : -1.0e4f) * 0.5f;
        *reinterpret_cast<float4*>(zbuf + idx) = zz;
        lmax = fmaxf(lmax, fmaxf(fmaxf(zz.x, zz.y), fmaxf(zz.z, zz.w)));
    }

    // ---- Block max (4 warps) ----
#pragma unroll
    for (int off = 16; off > 0; off >>= 1)
        lmax = fmaxf(lmax, __shfl_xor_sync(0xffffffffu, lmax, off));
    if (lane == 0) sh_max[wid] = lmax;
    if (t == 0) cnt = 0;
    __syncthreads();
    float rmax = sh_max[0];
#pragma unroll
    for (int i = 1; i < NWARP; ++i) rmax = fmaxf(rmax, sh_max[i]);
    const float thr = rmax - 1.0f;   // active iff z > thr

    // ---- Compact actives from shared (store v = z - rmax) ----
#pragma unroll
    for (int c = 0; c < VEC; ++c) {
        const int idx = c * (THREADS * 4) + t * 4;
        float4 zz = *reinterpret_cast<const float4*>(zbuf + idx);
#pragma unroll
        for (int j = 0; j < 4; ++j) {
            float zv = (&zz.x)[j];
            if (zv > thr) {
                int p = atomicAdd(&cnt, 1);          // warp-aggregated
                if (p < ACAP) abuf[p] = zv - rmax;
            }
        }
    }
    __syncthreads();

    // ---- Warp 0 solves tau; warps 1-3 wait at the barrier below ----
    if (wid == 0) {
        const int n = cnt;   // >= 1 (max elem has v = 0)
        float lo = -1.0f, hi = 0.0f;
        float tau;

        if (n <= CAP) {
            float v[4];
#pragma unroll
            for (int j = 0; j < 4; ++j) {
                int i = lane + 32 * j;
                v[j] = (i < n) ? abuf[i] : -2.0f;    // sentinel: never in support
            }
#pragma unroll 1
            for (int it = 0; it < NB; ++it) {
                const float tm = 0.5f * (lo + hi);
                float acc = 0.0f;
#pragma unroll
                for (int j = 0; j < 4; ++j) {
                    float d = fmaxf(v[j] - tm, 0.0f);
                    acc = fmaf(d, d, acc);
                }
                if (warp_sum(acc) >= 1.0f) lo = tm; else hi = tm;
            }
            float k = 0.0f, S1 = 0.0f, S2 = 0.0f;
#pragma unroll
            for (int j = 0; j < 4; ++j)
                if (v[j] > lo) { k += 1.0f; S1 += v[j]; S2 = fmaf(v[j], v[j], S2); }
            k = warp_sum(k); S1 = warp_sum(S1); S2 = warp_sum(S2);
            float disc = fmaxf(fmaf(S1, S1, -k * (S2 - 1.0f)), 0.0f);
            tau = (S1 - sqrtf(disc)) / k;
        } else if (n <= ACAP) {
#pragma unroll 1
            for (int it = 0; it < NB; ++it) {
                const float tm = 0.5f * (lo + hi);
                float acc = 0.0f;
                for (int i = lane; i < n; i += 32) {
                    float d = fmaxf(abuf[i] - tm, 0.0f);
                    acc = fmaf(d, d, acc);
                }
                if (warp_sum(acc) >= 1.0f) lo = tm; else hi = tm;
            }
            float k = 0.0f, S1 = 0.0f, S2 = 0.0f;
            for (int i = lane; i < n; i += 32) {
                float v = abuf[i];
                if (v > lo) { k += 1.0f; S1 += v; S2 = fmaf(v, v, S2); }
            }
            k = warp_sum(k); S1 = warp_sum(S1); S2 = warp_sum(S2);
            float disc = fmaxf(fmaf(S1, S1, -k * (S2 - 1.0f)), 0.0f);
            tau = (S1 - sqrtf(disc)) / k;
        } else {
            // pathological: scan the full row in shared
#pragma unroll 1
            for (int it = 0; it < NB; ++it) {
                const float tm = 0.5f * (lo + hi);
                float acc = 0.0f;
                for (int i = lane; i < COLS; i += 32) {
                    float d = fmaxf((zbuf[i] - rmax) - tm, 0.0f);
                    acc = fmaf(d, d, acc);
                }
                if (warp_sum(acc) >= 1.0f) lo = tm; else hi = tm;
            }
            float k = 0.0f, S1 = 0.0f, S2 = 0.0f;
            for (int i = lane; i < COLS; i += 32) {
                float v = zbuf[i] - rmax;
                if (v > lo) { k += 1.0f; S1 += v; S2 = fmaf(v, v, S2); }
            }
            k = warp_sum(k); S1 = warp_sum(S1); S2 = warp_sum(S2);
            float disc = fmaxf(fmaf(S1, S1, -k * (S2 - 1.0f)), 0.0f);
            tau = (S1 - sqrtf(disc)) / k;
        }
        if (lane == 0) sh_tau = tau;
    }
    __syncthreads();
    const float taup = sh_tau + rmax;    // p = max(z - taup, 0)^2

    // ---- Store p from shared ----
#pragma unroll
    for (int c = 0; c < VEC; ++c) {
        const int idx = c * (THREADS * 4) + t * 4;
        float4 zz = *reinterpret_cast<const float4*>(zbuf + idx);
        float d0 = fmaxf(zz.x - taup, 0.0f);
        float d1 = fmaxf(zz.y - taup, 0.0f);
        float d2 = fmaxf(zz.z - taup, 0.0f);
        float d3 = fmaxf(zz.w - taup, 0.0f);
        float4 p;
        p.x = d0*d0; p.y = d1*d1; p.z = d2*d2; p.w = d3*d3;
        __stcs(reinterpret_cast<float4*>(o + idx), p);
    }
}

extern "C" void kernel_launch(void* const* d_in, const int* in_sizes, int n_in,
                              void* d_out, int out_size) {
    const float* scores = (const float*)d_in[0];
    const int*   mask   = (const int*)d_in[1];
    float* out = (float*)d_out;
    const int rows = in_sizes[0] / COLS;
    entmax15_kernel<<<rows, THREADS>>>(scores, mask, out);
}